// round 3
// baseline (speedup 1.0000x reference)
#include <cuda_runtime.h>
#include <cuda_bf16.h>
#include <math.h>

#define Bsz 64
#define Lsz 512
#define DIN 1024
#define Hsz 1024
#define Gsz 4096
#define ML (Bsz*Lsz)            // 32768
#define OUTN ((size_t)Bsz*Lsz*Hsz) // 33554432

// ---------------- scratch (static device allocations) ----------------
__device__ float g_xproj[(size_t)ML*Gsz];                 // 512 MB
__device__ __nv_bfloat16 g_xhi[(size_t)ML*DIN];
__device__ __nv_bfloat16 g_xlo[(size_t)ML*DIN];
__device__ __nv_bfloat16 g_wxhi[(size_t)Gsz*DIN];
__device__ __nv_bfloat16 g_wxlo[(size_t)Gsz*DIN];
__device__ __nv_bfloat16 g_whhi[(size_t)Gsz*Hsz];
__device__ __nv_bfloat16 g_whlo[(size_t)Gsz*Hsz];
__device__ __nv_bfloat16 g_hhi3[3][Bsz*Hsz];
__device__ __nv_bfloat16 g_hlo3[3][Bsz*Hsz];
__device__ unsigned g_rc[8];    // region counters (wavefront sync)

// ---------------- helpers ----------------
__device__ __forceinline__ void mma16816(float* c, const unsigned* a, const unsigned* b) {
    asm volatile(
        "mma.sync.aligned.m16n8k16.row.col.f32.bf16.bf16.f32 "
        "{%0,%1,%2,%3}, {%4,%5,%6,%7}, {%8,%9}, {%0,%1,%2,%3};\n"
        : "+f"(c[0]), "+f"(c[1]), "+f"(c[2]), "+f"(c[3])
        : "r"(a[0]), "r"(a[1]), "r"(a[2]), "r"(a[3]), "r"(b[0]), "r"(b[1]));
}

__device__ __forceinline__ void ldsm_x4(unsigned* r, const void* p) {
    unsigned a = (unsigned)__cvta_generic_to_shared(p);
    asm volatile("ldmatrix.sync.aligned.m8n8.x4.shared.b16 {%0,%1,%2,%3}, [%4];\n"
        : "=r"(r[0]), "=r"(r[1]), "=r"(r[2]), "=r"(r[3]) : "r"(a));
}

__device__ __forceinline__ void cp16(void* dst, const void* src) {
    unsigned d = (unsigned)__cvta_generic_to_shared(dst);
    asm volatile("cp.async.cg.shared.global [%0], [%1], 16;\n" :: "r"(d), "l"(src));
}
__device__ __forceinline__ void cp_commit() { asm volatile("cp.async.commit_group;\n"); }
__device__ __forceinline__ void cp_wait1()  { asm volatile("cp.async.wait_group 1;\n"); }
__device__ __forceinline__ void cp_wait0()  { asm volatile("cp.async.wait_group 0;\n"); }

__device__ __forceinline__ void bar_compute() {   // warps 0-7 only
    asm volatile("bar.sync 1, 256;\n" ::: "memory");
}

__device__ __forceinline__ float sigmoidf_(float x) {
    return 1.0f / (1.0f + __expf(-x));
}

// ---------------- split kernels ----------------
__global__ void split_x_kernel(const float* __restrict__ x) {
    size_t stride = (size_t)gridDim.x * blockDim.x;
    for (size_t i = (size_t)blockIdx.x * blockDim.x + threadIdx.x;
         i < (size_t)ML * DIN; i += stride) {
        float v = x[i];
        __nv_bfloat16 hi = __float2bfloat16(v);
        g_xhi[i] = hi;
        g_xlo[i] = __float2bfloat16(v - __bfloat162float(hi));
    }
}

__global__ void split_w_kernel(const float* __restrict__ W) {
    size_t stride = (size_t)gridDim.x * blockDim.x;
    for (size_t i = (size_t)blockIdx.x * blockDim.x + threadIdx.x;
         i < (size_t)Gsz * (Hsz + DIN); i += stride) {
        int r = (int)(i >> 11);
        int c = (int)(i & 2047);
        float v = W[i];
        __nv_bfloat16 hi = __float2bfloat16(v);
        __nv_bfloat16 lo = __float2bfloat16(v - __bfloat162float(hi));
        size_t d = (size_t)r * 1024 + (c & 1023);
        if (c < 1024) { g_whhi[d] = hi; g_whlo[d] = lo; }
        else          { g_wxhi[d] = hi; g_wxlo[d] = lo; }
    }
}

__global__ void init_kernel() {
    int i = blockIdx.x * blockDim.x + threadIdx.x;
    if (i < 8) g_rc[i] = 0;
    if (i < Bsz * Hsz) {
        __nv_bfloat16 z = __float2bfloat16(0.0f);
        g_hhi3[0][i] = z;
        g_hlo3[0][i] = z;
    }
}

// ---------------- phase 1: x_proj GEMM (split bf16, 3 mma, 3-stage cp.async, ldmatrix) ----------------
#define P1_BM 128
#define P1_BN 128
#define P1_BK 32
#define P1_ROW 40   // 32 + 8 pad: 80B rows, 16B aligned, stride 5 units (coprime with 8)
#define P1_HALF (128 * P1_ROW)                    // elems per (hi/lo) plane
#define P1_BUF  (2 * P1_HALF)                     // elems per stage (A or B)
#define P1_SMEM ((size_t)3 * P1_BUF * 2 * 2)      // 3 stages * (A+B) * bf16  = 122880 B

__global__ __launch_bounds__(256) void xproj_kernel(const float* __restrict__ bias) {
    extern __shared__ __nv_bfloat16 sm1[];
    __nv_bfloat16* Asm = sm1;                      // [3][2][128][40]
    __nv_bfloat16* Bsm = sm1 + 3 * P1_BUF;         // [3][2][128][40]

    const int tid = threadIdx.x;
    const int wid = tid >> 5, lane = tid & 31;
    const int wm = wid & 3;     // rows wm*32 (2 m-tiles of 16)
    const int wn = wid >> 2;    // cols wn*64 (8 n-tiles of 8)
    const int m0 = blockIdx.y * P1_BM;
    const int n0 = blockIdx.x * P1_BN;

    float acc[2][8][4];
    #pragma unroll
    for (int i = 0; i < 2; ++i)
        #pragma unroll
        for (int j = 0; j < 8; ++j)
            #pragma unroll
            for (int k = 0; k < 4; ++k) acc[i][j][k] = 0.0f;

    const int lrow = tid >> 1;            // 0..127
    const int lcb  = (tid & 1) * 16;      // 0 or 16

    const __nv_bfloat16* srcAh = g_xhi  + (size_t)(m0 + lrow) * DIN + lcb;
    const __nv_bfloat16* srcAl = g_xlo  + (size_t)(m0 + lrow) * DIN + lcb;
    const __nv_bfloat16* srcBh = g_wxhi + (size_t)(n0 + lrow) * DIN + lcb;
    const __nv_bfloat16* srcBl = g_wxlo + (size_t)(n0 + lrow) * DIN + lcb;

    auto stage = [&](int s, int k0) {
        __nv_bfloat16* A = Asm + s * P1_BUF;
        __nv_bfloat16* B = Bsm + s * P1_BUF;
        cp16(A + lrow * P1_ROW + lcb,                 srcAh + k0);
        cp16(A + lrow * P1_ROW + lcb + 8,             srcAh + k0 + 8);
        cp16(A + P1_HALF + lrow * P1_ROW + lcb,       srcAl + k0);
        cp16(A + P1_HALF + lrow * P1_ROW + lcb + 8,   srcAl + k0 + 8);
        cp16(B + lrow * P1_ROW + lcb,                 srcBh + k0);
        cp16(B + lrow * P1_ROW + lcb + 8,             srcBh + k0 + 8);
        cp16(B + P1_HALF + lrow * P1_ROW + lcb,       srcBl + k0);
        cp16(B + P1_HALF + lrow * P1_ROW + lcb + 8,   srcBl + k0 + 8);
        cp_commit();
    };

    stage(0, 0);
    stage(1, P1_BK);

    // ldmatrix lane-address components
    const int aRow = lane & 15;
    const int aCol = (lane >> 4) << 3;
    const int bRow = ((lane >> 4) << 3) + (lane & 7);
    const int bCol = ((lane >> 3) & 1) << 3;

    const int NIT = DIN / P1_BK;   // 32
    for (int it = 0; it < NIT; ++it) {
        const int s = it % 3;
        cp_wait1();
        __syncthreads();
        if (it + 2 < NIT) stage((it + 2) % 3, (it + 2) * P1_BK);

        const __nv_bfloat16* A = Asm + s * P1_BUF;
        const __nv_bfloat16* B = Bsm + s * P1_BUF;

        #pragma unroll
        for (int kk = 0; kk < 2; ++kk) {
            const int kb = kk * 16;
            unsigned ahi[2][4], alo[2][4];
            #pragma unroll
            for (int mt = 0; mt < 2; ++mt) {
                const int r0 = wm * 32 + mt * 16;
                ldsm_x4(ahi[mt], A + (r0 + aRow) * P1_ROW + kb + aCol);
                ldsm_x4(alo[mt], A + P1_HALF + (r0 + aRow) * P1_ROW + kb + aCol);
            }
            #pragma unroll
            for (int p = 0; p < 4; ++p) {
                const int nb0 = wn * 64 + p * 16;
                unsigned bh[4], bl[4];
                ldsm_x4(bh, B + (nb0 + bRow) * P1_ROW + kb + bCol);
                ldsm_x4(bl, B + P1_HALF + (nb0 + bRow) * P1_ROW + kb + bCol);
                #pragma unroll
                for (int mt = 0; mt < 2; ++mt) {
                    #pragma unroll
                    for (int q = 0; q < 2; ++q) {
                        float* a = acc[mt][p * 2 + q];
                        mma16816(a, ahi[mt], bh + 2 * q);
                        mma16816(a, ahi[mt], bl + 2 * q);
                        mma16816(a, alo[mt], bh + 2 * q);
                    }
                }
            }
        }
    }

    // epilogue: +bias, store fp32
    const int g = lane >> 2, tg = lane & 3;
    #pragma unroll
    for (int nt = 0; nt < 8; ++nt) {
        const int c = n0 + wn * 64 + nt * 8 + 2 * tg;
        const float bv0 = bias[c], bv1 = bias[c + 1];
        #pragma unroll
        for (int mt = 0; mt < 2; ++mt) {
            const int r0 = m0 + wm * 32 + mt * 16 + g;
            float2 v0 = make_float2(acc[mt][nt][0] + bv0, acc[mt][nt][1] + bv1);
            float2 v1 = make_float2(acc[mt][nt][2] + bv0, acc[mt][nt][3] + bv1);
            *(float2*)&g_xproj[(size_t)r0 * Gsz + c]       = v0;
            *(float2*)&g_xproj[(size_t)(r0 + 8) * Gsz + c] = v1;
        }
    }
}

// ---------------- phase 2: persistent recurrent LSTM (warp-specialized, wavefront sync) ----------------
#define NBLK2 128
#define HPERB 8
#define NG 32
#define WPAD 8           // wh row length 1032 (2064B; stride 129 units, coprime 8)
#define KC 128
#define HTPAD 8          // htile row length 136 (272B; stride 17 units)
#define NCHUNK (Hsz / KC)
#define NTH2 288         // 8 compute warps + 1 producer warp

#define SM_WH   (NG * (Hsz + WPAD))
#define SM_HT   (Bsz * (KC + HTPAD))
#define SMEM_P2 ((size_t)(2*SM_WH + 4*SM_HT) * 2 + (size_t)(Bsz*NG + Bsz*HPERB) * 4)

__global__ __launch_bounds__(NTH2, 1) void lstm_kernel(float* __restrict__ out) {
    extern __shared__ char smem[];
    __nv_bfloat16* whhi = (__nv_bfloat16*)smem;               // [NG][1032]
    __nv_bfloat16* whlo = whhi + SM_WH;
    __nv_bfloat16* hthi[2];
    __nv_bfloat16* htlo[2];
    hthi[0] = whlo + SM_WH;                                    // [64][136]
    htlo[0] = hthi[0] + SM_HT;
    hthi[1] = htlo[0] + SM_HT;
    htlo[1] = hthi[1] + SM_HT;
    float* gates = (float*)(htlo[1] + SM_HT);                  // [64][32]
    float* csm   = gates + Bsz * NG;                           // [64][8]

    __shared__ volatile int s_full;    // last staged chunk (global idx)+1
    __shared__ volatile int s_empty;   // last consumed chunk (global idx)+1

    const int tid = threadIdx.x;
    const int wid = tid >> 5, lane = tid & 31;
    const int j0 = blockIdx.x * HPERB;
    const int region = blockIdx.x >> 4;   // which K-region this block's h columns fall in

    // Wh slice into SMEM (all 288 threads)
    for (int i = tid; i < NG * (Hsz / 8); i += NTH2) {
        const int n = i >> 7;
        const int cu = i & 127;
        const int q = n >> 3, jj = n & 7;
        const size_t src = (size_t)(q * 1024 + j0 + jj) * Hsz + cu * 8;
        *(uint4*)&whhi[n * (Hsz + WPAD) + cu * 8] = *(const uint4*)(g_whhi + src);
        *(uint4*)&whlo[n * (Hsz + WPAD) + cu * 8] = *(const uint4*)(g_whlo + src);
    }
    for (int i = tid; i < Bsz * HPERB; i += NTH2) csm[i] = 0.0f;
    if (tid == 0) { s_full = 0; s_empty = 0; }
    __syncthreads();

    if (wid == 8) {
        // ================= producer warp =================
        for (int t = 0; t < Lsz; ++t) {
            const __nv_bfloat16* shi = &g_hhi3[t % 3][0];
            const __nv_bfloat16* slo = &g_hlo3[t % 3][0];
            const unsigned rcw = (unsigned)t * 16;

            for (int kc = 0; kc < NCHUNK; ++kc) {
                const int G = t * NCHUNK + kc;
                // buffer free? (buf reused from chunk G-2)
                while (s_empty < G - 1) { }
                // region data ready? (written by 16 owner blocks at step t-1)
                if (lane == 0) {
                    while (*(volatile unsigned*)&g_rc[kc] < rcw) { }
                }
                __syncwarp();
                __threadfence();   // acquire for peer-block h writes

                const int buf = kc & 1;
                #pragma unroll 8
                for (int q = 0; q < 32; ++q) {
                    const int i = lane + q * 32;
                    const int row = i >> 4, cu = i & 15;
                    const size_t src = (size_t)row * Hsz + kc * KC + cu * 8;
                    cp16(&hthi[buf][row * (KC + HTPAD) + cu * 8], shi + src);
                    cp16(&htlo[buf][row * (KC + HTPAD) + cu * 8], slo + src);
                }
                cp_commit();

                if (kc == NCHUNK - 1) {
                    cp_wait0();
                    __threadfence_block();
                    if (lane == 0) s_full = G + 1;
                    __syncwarp();
                } else if (kc >= 1) {
                    cp_wait1();
                    __threadfence_block();
                    if (lane == 0) s_full = G;   // chunk G-1 ready
                    __syncwarp();
                }
            }
        }
    } else {
        // ================= compute warps (0-7) =================
        const int g = lane >> 2, tg = lane & 3;
        const int wm = wid & 3;
        const int wn = wid >> 2;
        const int aRow = lane & 15;
        const int aCol = (lane >> 4) << 3;
        const int bRow = wn * 16 + ((lane >> 4) << 3) + (lane & 7);
        const int bCol = ((lane >> 3) & 1) << 3;

        const int b_0 = tid >> 3, jj_0 = tid & 7;
        const int b_1 = (tid + 256) >> 3, jj_1 = (tid + 256) & 7;

        // prefetch xproj for step 0
        float xp[8];
        {
            const size_t base0 = ((size_t)b_0 * Lsz) * Gsz + j0 + jj_0;
            const size_t base1 = ((size_t)b_1 * Lsz) * Gsz + j0 + jj_1;
            xp[0] = __ldg(g_xproj + base0);
            xp[1] = __ldg(g_xproj + base0 + 1024);
            xp[2] = __ldg(g_xproj + base0 + 2048);
            xp[3] = __ldg(g_xproj + base0 + 3072);
            xp[4] = __ldg(g_xproj + base1);
            xp[5] = __ldg(g_xproj + base1 + 1024);
            xp[6] = __ldg(g_xproj + base1 + 2048);
            xp[7] = __ldg(g_xproj + base1 + 3072);
        }

        for (int t = 0; t < Lsz; ++t) {
            float acc[2][4];
            #pragma unroll
            for (int i = 0; i < 2; ++i)
                #pragma unroll
                for (int k = 0; k < 4; ++k) acc[i][k] = 0.0f;

            for (int kc = 0; kc < NCHUNK; ++kc) {
                const int G = t * NCHUNK + kc;
                while (s_full < G + 1) { }
                __threadfence_block();

                const __nv_bfloat16* thi = hthi[kc & 1];
                const __nv_bfloat16* tlo = htlo[kc & 1];

                #pragma unroll
                for (int ks = 0; ks < KC / 16; ++ks) {
                    const int kb = ks * 16;
                    unsigned ahi[4], alo[4], bh[4], bl[4];
                    ldsm_x4(ahi, thi + (wm * 16 + aRow) * (KC + HTPAD) + kb + aCol);
                    ldsm_x4(alo, tlo + (wm * 16 + aRow) * (KC + HTPAD) + kb + aCol);
                    const int koff = kc * KC + kb + bCol;
                    ldsm_x4(bh, whhi + bRow * (Hsz + WPAD) + koff);
                    ldsm_x4(bl, whlo + bRow * (Hsz + WPAD) + koff);
                    mma16816(acc[0], ahi, bh);
                    mma16816(acc[0], ahi, bl);
                    mma16816(acc[0], alo, bh);
                    mma16816(acc[1], ahi, bh + 2);
                    mma16816(acc[1], ahi, bl + 2);
                    mma16816(acc[1], alo, bh + 2);
                }

                bar_compute();
                if (tid == 0) s_empty = G + 1;
            }

            // gate pre-activations -> SMEM
            #pragma unroll
            for (int nt = 0; nt < 2; ++nt) {
                const int c = wn * 16 + nt * 8 + 2 * tg;
                const int r = wm * 16 + g;
                gates[r * NG + c]           = acc[nt][0];
                gates[r * NG + c + 1]       = acc[nt][1];
                gates[(r + 8) * NG + c]     = acc[nt][2];
                gates[(r + 8) * NG + c + 1] = acc[nt][3];
            }
            bar_compute();

            // LSTM cell (512 items), write h into buffer (t+1)%3
            const int nb = (t + 1) % 3;
            {
                const float pf = gates[b_0 * NG + 0 * 8 + jj_0] + xp[0];
                const float pi = gates[b_0 * NG + 1 * 8 + jj_0] + xp[1];
                const float pg = gates[b_0 * NG + 2 * 8 + jj_0] + xp[2];
                const float po = gates[b_0 * NG + 3 * 8 + jj_0] + xp[3];
                const float f = sigmoidf_(pf);
                const float ii = sigmoidf_(pi);
                const float gg = tanhf(pg);
                const float o = sigmoidf_(po);
                const float c_new = f * csm[tid] + ii * gg;
                csm[tid] = c_new;
                const float h = o * tanhf(c_new);
                out[((size_t)b_0 * Lsz + t) * Hsz + j0 + jj_0] = h;
                const __nv_bfloat16 hh = __float2bfloat16(h);
                g_hhi3[nb][b_0 * Hsz + j0 + jj_0] = hh;
                g_hlo3[nb][b_0 * Hsz + j0 + jj_0] = __float2bfloat16(h - __bfloat162float(hh));
            }
            {
                const float pf = gates[b_1 * NG + 0 * 8 + jj_1] + xp[4];
                const float pi = gates[b_1 * NG + 1 * 8 + jj_1] + xp[5];
                const float pg = gates[b_1 * NG + 2 * 8 + jj_1] + xp[6];
                const float po = gates[b_1 * NG + 3 * 8 + jj_1] + xp[7];
                const float f = sigmoidf_(pf);
                const float ii = sigmoidf_(pi);
                const float gg = tanhf(pg);
                const float o = sigmoidf_(po);
                const float c_new = f * csm[tid + 256] + ii * gg;
                csm[tid + 256] = c_new;
                const float h = o * tanhf(c_new);
                out[((size_t)b_1 * Lsz + t) * Hsz + j0 + jj_1] = h;
                const __nv_bfloat16 hh = __float2bfloat16(h);
                g_hhi3[nb][b_1 * Hsz + j0 + jj_1] = hh;
                g_hlo3[nb][b_1 * Hsz + j0 + jj_1] = __float2bfloat16(h - __bfloat162float(hh));
            }

            __threadfence();
            bar_compute();
            if (tid == 0) atomicAdd(&g_rc[region], 1u);

            // prefetch xproj for next step (latency hidden under next chunk waits)
            if (t + 1 < Lsz) {
                const size_t base0 = ((size_t)b_0 * Lsz + (t + 1)) * Gsz + j0 + jj_0;
                const size_t base1 = ((size_t)b_1 * Lsz + (t + 1)) * Gsz + j0 + jj_1;
                xp[0] = __ldg(g_xproj + base0);
                xp[1] = __ldg(g_xproj + base0 + 1024);
                xp[2] = __ldg(g_xproj + base0 + 2048);
                xp[3] = __ldg(g_xproj + base0 + 3072);
                xp[4] = __ldg(g_xproj + base1);
                xp[5] = __ldg(g_xproj + base1 + 1024);
                xp[6] = __ldg(g_xproj + base1 + 2048);
                xp[7] = __ldg(g_xproj + base1 + 3072);
            }
        }

        // finals
        {
            const float hv0 = out[((size_t)b_0 * Lsz + (Lsz - 1)) * Hsz + j0 + jj_0];
            out[OUTN + (size_t)b_0 * Hsz + j0 + jj_0] = hv0;
            out[OUTN + (size_t)Bsz * Hsz + (size_t)b_0 * Hsz + j0 + jj_0] = csm[tid];
            const float hv1 = out[((size_t)b_1 * Lsz + (Lsz - 1)) * Hsz + j0 + jj_1];
            out[OUTN + (size_t)b_1 * Hsz + j0 + jj_1] = hv1;
            out[OUTN + (size_t)Bsz * Hsz + (size_t)b_1 * Hsz + j0 + jj_1] = csm[tid + 256];
        }
    }
}

// ---------------- launcher ----------------
extern "C" void kernel_launch(void* const* d_in, const int* in_sizes, int n_in,
                              void* d_out, int out_size) {
    const float* x = (const float*)d_in[0];
    const float* W = (const float*)d_in[1];
    const float* b = (const float*)d_in[2];
    float* out = (float*)d_out;

    split_x_kernel<<<2048, 256>>>(x);
    split_w_kernel<<<1024, 256>>>(W);
    init_kernel<<<256, 256>>>();

    cudaFuncSetAttribute(xproj_kernel, cudaFuncAttributeMaxDynamicSharedMemorySize,
                         (int)P1_SMEM);
    dim3 g1(Gsz / P1_BN, ML / P1_BM);   // (32, 256)
    xproj_kernel<<<g1, 256, P1_SMEM>>>(b);

    cudaFuncSetAttribute(lstm_kernel, cudaFuncAttributeMaxDynamicSharedMemorySize,
                         (int)SMEM_P2);
    lstm_kernel<<<NBLK2, NTH2, SMEM_P2>>>(out);
}

// round 4
// speedup vs baseline: 1.4703x; 1.4703x over previous
#include <cuda_runtime.h>
#include <cuda_bf16.h>
#include <math.h>

#define Bsz 64
#define Lsz 512
#define DIN 1024
#define Hsz 1024
#define Gsz 4096
#define ML (Bsz*Lsz)            // 32768
#define OUTN ((size_t)Bsz*Lsz*Hsz) // 33554432

// ---------------- scratch (static device allocations) ----------------
__device__ float g_xproj[(size_t)ML*Gsz];                 // 512 MB
__device__ __nv_bfloat16 g_xhi[(size_t)ML*DIN];
__device__ __nv_bfloat16 g_xlo[(size_t)ML*DIN];
__device__ __nv_bfloat16 g_wxhi[(size_t)Gsz*DIN];
__device__ __nv_bfloat16 g_wxlo[(size_t)Gsz*DIN];
__device__ __nv_bfloat16 g_whhi[(size_t)Gsz*Hsz];
__device__ __nv_bfloat16 g_whlo[(size_t)Gsz*Hsz];
__device__ __nv_bfloat16 g_hhi3[3][Bsz*Hsz];
__device__ __nv_bfloat16 g_hlo3[3][Bsz*Hsz];
__device__ unsigned g_rc[8];    // per-K-region step counters

// ---------------- helpers ----------------
__device__ __forceinline__ void mma16816(float* c, const unsigned* a, const unsigned* b) {
    asm volatile(
        "mma.sync.aligned.m16n8k16.row.col.f32.bf16.bf16.f32 "
        "{%0,%1,%2,%3}, {%4,%5,%6,%7}, {%8,%9}, {%0,%1,%2,%3};\n"
        : "+f"(c[0]), "+f"(c[1]), "+f"(c[2]), "+f"(c[3])
        : "r"(a[0]), "r"(a[1]), "r"(a[2]), "r"(a[3]), "r"(b[0]), "r"(b[1]));
}

__device__ __forceinline__ void ldsm_x4(unsigned* r, const void* p) {
    unsigned a = (unsigned)__cvta_generic_to_shared(p);
    asm volatile("ldmatrix.sync.aligned.m8n8.x4.shared.b16 {%0,%1,%2,%3}, [%4];\n"
        : "=r"(r[0]), "=r"(r[1]), "=r"(r[2]), "=r"(r[3]) : "r"(a));
}

__device__ __forceinline__ void cp16(void* dst, const void* src) {
    unsigned d = (unsigned)__cvta_generic_to_shared(dst);
    asm volatile("cp.async.cg.shared.global [%0], [%1], 16;\n" :: "r"(d), "l"(src));
}
__device__ __forceinline__ void cp_commit() { asm volatile("cp.async.commit_group;\n"); }
__device__ __forceinline__ void cp_wait1()  { asm volatile("cp.async.wait_group 1;\n"); }
__device__ __forceinline__ void cp_wait0()  { asm volatile("cp.async.wait_group 0;\n"); }

__device__ __forceinline__ unsigned ld_acq(const unsigned* p) {
    unsigned v;
    asm volatile("ld.acquire.gpu.global.u32 %0, [%1];" : "=r"(v) : "l"(p));
    return v;
}

__device__ __forceinline__ float sigmoidf_(float x) {
    return 1.0f / (1.0f + __expf(-x));
}

// ---------------- split kernels ----------------
__global__ void split_x_kernel(const float* __restrict__ x) {
    size_t stride = (size_t)gridDim.x * blockDim.x;
    for (size_t i = (size_t)blockIdx.x * blockDim.x + threadIdx.x;
         i < (size_t)ML * DIN; i += stride) {
        float v = x[i];
        __nv_bfloat16 hi = __float2bfloat16(v);
        g_xhi[i] = hi;
        g_xlo[i] = __float2bfloat16(v - __bfloat162float(hi));
    }
}

__global__ void split_w_kernel(const float* __restrict__ W) {
    size_t stride = (size_t)gridDim.x * blockDim.x;
    for (size_t i = (size_t)blockIdx.x * blockDim.x + threadIdx.x;
         i < (size_t)Gsz * (Hsz + DIN); i += stride) {
        int r = (int)(i >> 11);
        int c = (int)(i & 2047);
        float v = W[i];
        __nv_bfloat16 hi = __float2bfloat16(v);
        __nv_bfloat16 lo = __float2bfloat16(v - __bfloat162float(hi));
        size_t d = (size_t)r * 1024 + (c & 1023);
        if (c < 1024) { g_whhi[d] = hi; g_whlo[d] = lo; }
        else          { g_wxhi[d] = hi; g_wxlo[d] = lo; }
    }
}

__global__ void init_kernel() {
    int i = blockIdx.x * blockDim.x + threadIdx.x;
    if (i < 8) g_rc[i] = 0;
    if (i < Bsz * Hsz) {
        __nv_bfloat16 z = __float2bfloat16(0.0f);
        g_hhi3[0][i] = z;
        g_hlo3[0][i] = z;
    }
}

// ---------------- phase 1: x_proj GEMM (split bf16, 3 mma, 2-stage cp.async, ldmatrix) ----------------
#define P1_BM 128
#define P1_BN 128
#define P1_BK 32
#define P1_ROW 40   // 32 + 8 pad

__global__ __launch_bounds__(256) void xproj_kernel(const float* __restrict__ bias) {
    __shared__ __nv_bfloat16 As[2][2][P1_BM][P1_ROW];  // [buf][hi/lo] — 40960 B
    __shared__ __nv_bfloat16 Bs[2][2][P1_BN][P1_ROW];  // 40960 B  (total 80 KB)

    const int tid = threadIdx.x;
    const int wid = tid >> 5, lane = tid & 31;
    const int wm = wid & 3;     // rows wm*32 (2 m-tiles of 16)
    const int wn = wid >> 2;    // cols wn*64
    const int m0 = blockIdx.y * P1_BM;
    const int n0 = blockIdx.x * P1_BN;

    float acc[2][8][4];
    #pragma unroll
    for (int i = 0; i < 2; ++i)
        #pragma unroll
        for (int j = 0; j < 8; ++j)
            #pragma unroll
            for (int k = 0; k < 4; ++k) acc[i][j][k] = 0.0f;

    const int lrow = tid >> 1;            // 0..127
    const int lcb  = (tid & 1) * 16;      // 0 or 16

    const __nv_bfloat16* srcAh = g_xhi  + (size_t)(m0 + lrow) * DIN + lcb;
    const __nv_bfloat16* srcAl = g_xlo  + (size_t)(m0 + lrow) * DIN + lcb;
    const __nv_bfloat16* srcBh = g_wxhi + (size_t)(n0 + lrow) * DIN + lcb;
    const __nv_bfloat16* srcBl = g_wxlo + (size_t)(n0 + lrow) * DIN + lcb;

    auto stage = [&](int buf, int k0) {
        cp16(&As[buf][0][lrow][lcb],     srcAh + k0);
        cp16(&As[buf][0][lrow][lcb + 8], srcAh + k0 + 8);
        cp16(&As[buf][1][lrow][lcb],     srcAl + k0);
        cp16(&As[buf][1][lrow][lcb + 8], srcAl + k0 + 8);
        cp16(&Bs[buf][0][lrow][lcb],     srcBh + k0);
        cp16(&Bs[buf][0][lrow][lcb + 8], srcBh + k0 + 8);
        cp16(&Bs[buf][1][lrow][lcb],     srcBl + k0);
        cp16(&Bs[buf][1][lrow][lcb + 8], srcBl + k0 + 8);
        cp_commit();
    };

    stage(0, 0);

    // ldmatrix lane-address components
    const int aRow = lane & 15;
    const int aCol = (lane >> 4) << 3;
    const int bRow = ((lane >> 4) << 3) + (lane & 7);
    const int bCol = ((lane >> 3) & 1) << 3;

    for (int k0 = 0; k0 < DIN; k0 += P1_BK) {
        const int buf = (k0 >> 5) & 1;
        const bool more = (k0 + P1_BK) < DIN;
        if (more) stage(buf ^ 1, k0 + P1_BK);
        if (more) cp_wait1(); else cp_wait0();
        __syncthreads();

        #pragma unroll
        for (int kk = 0; kk < 2; ++kk) {
            const int kb = kk * 16;
            unsigned ahi[2][4], alo[2][4];
            #pragma unroll
            for (int mt = 0; mt < 2; ++mt) {
                const int r0 = wm * 32 + mt * 16;
                ldsm_x4(ahi[mt], &As[buf][0][r0 + aRow][kb + aCol]);
                ldsm_x4(alo[mt], &As[buf][1][r0 + aRow][kb + aCol]);
            }
            #pragma unroll
            for (int p = 0; p < 4; ++p) {
                const int nb0 = wn * 64 + p * 16;
                unsigned bh[4], bl[4];
                ldsm_x4(bh, &Bs[buf][0][nb0 + bRow][kb + bCol]);
                ldsm_x4(bl, &Bs[buf][1][nb0 + bRow][kb + bCol]);
                #pragma unroll
                for (int mt = 0; mt < 2; ++mt) {
                    #pragma unroll
                    for (int q = 0; q < 2; ++q) {
                        float* a = acc[mt][p * 2 + q];
                        mma16816(a, ahi[mt], bh + 2 * q);
                        mma16816(a, ahi[mt], bl + 2 * q);
                        mma16816(a, alo[mt], bh + 2 * q);
                    }
                }
            }
        }
        __syncthreads();
    }

    // epilogue: +bias, store fp32
    const int g = lane >> 2, tg = lane & 3;
    #pragma unroll
    for (int nt = 0; nt < 8; ++nt) {
        const int c = n0 + wn * 64 + nt * 8 + 2 * tg;
        const float bv0 = bias[c], bv1 = bias[c + 1];
        #pragma unroll
        for (int mt = 0; mt < 2; ++mt) {
            const int r0 = m0 + wm * 32 + mt * 16 + g;
            float2 v0 = make_float2(acc[mt][nt][0] + bv0, acc[mt][nt][1] + bv1);
            float2 v1 = make_float2(acc[mt][nt][2] + bv0, acc[mt][nt][3] + bv1);
            *(float2*)&g_xproj[(size_t)r0 * Gsz + c]       = v0;
            *(float2*)&g_xproj[(size_t)(r0 + 8) * Gsz + c] = v1;
        }
    }
}

// ---------------- phase 2: persistent recurrent LSTM (round-2 skeleton + ldmatrix + region wavefront) ----------------
#define NBLK2 128
#define HPERB 8
#define NG 32
#define WPAD 8           // wh row length 1032
#define KC 128
#define HTPAD 8          // htile row length 136
#define NCHUNK (Hsz / KC)

#define SM_WH   (NG * (Hsz + WPAD))
#define SM_HT   (Bsz * (KC + HTPAD))
#define SMEM_P2 ((size_t)(2*SM_WH + 4*SM_HT) * 2 + (size_t)(Bsz*NG + Bsz*HPERB) * 4)

__global__ __launch_bounds__(256, 1) void lstm_kernel(float* __restrict__ out) {
    extern __shared__ char smem[];
    __nv_bfloat16* whhi = (__nv_bfloat16*)smem;               // [NG][1032]
    __nv_bfloat16* whlo = whhi + SM_WH;
    __nv_bfloat16* hthi[2];
    __nv_bfloat16* htlo[2];
    hthi[0] = whlo + SM_WH;                                    // [64][136]
    htlo[0] = hthi[0] + SM_HT;
    hthi[1] = htlo[0] + SM_HT;
    htlo[1] = hthi[1] + SM_HT;
    float* gates = (float*)(htlo[1] + SM_HT);                  // [64][32]
    float* csm   = gates + Bsz * NG;                           // [64][8]

    const int tid = threadIdx.x;
    const int wid = tid >> 5, lane = tid & 31;
    const int g = lane >> 2, tg = lane & 3;
    const int wm = wid & 3;      // rows wm*16
    const int wn = wid >> 2;     // cols wn*16
    const int j0 = blockIdx.x * HPERB;
    const int region = blockIdx.x >> 4;

    // ldmatrix lane-address components
    const int aRow = lane & 15;
    const int aCol = (lane >> 4) << 3;
    const int bRow = wn * 16 + ((lane >> 4) << 3) + (lane & 7);
    const int bCol = ((lane >> 3) & 1) << 3;

    // Wh slice into SMEM
    for (int i = tid; i < NG * (Hsz / 8); i += 256) {
        const int n = i >> 7;
        const int cu = i & 127;
        const int q = n >> 3, jj = n & 7;
        const size_t src = (size_t)(q * 1024 + j0 + jj) * Hsz + cu * 8;
        *(uint4*)&whhi[n * (Hsz + WPAD) + cu * 8] = *(const uint4*)(g_whhi + src);
        *(uint4*)&whlo[n * (Hsz + WPAD) + cu * 8] = *(const uint4*)(g_whlo + src);
    }
    for (int i = tid; i < Bsz * HPERB; i += 256) csm[i] = 0.0f;
    __syncthreads();

    const int b_0 = tid >> 3, jj_0 = tid & 7;
    const int b_1 = (tid + 256) >> 3, jj_1 = (tid + 256) & 7;

    // prefetch xproj for step 0
    float xp[8];
    {
        const size_t base0 = ((size_t)b_0 * Lsz) * Gsz + j0 + jj_0;
        const size_t base1 = ((size_t)b_1 * Lsz) * Gsz + j0 + jj_1;
        xp[0] = __ldg(g_xproj + base0);
        xp[1] = __ldg(g_xproj + base0 + 1024);
        xp[2] = __ldg(g_xproj + base0 + 2048);
        xp[3] = __ldg(g_xproj + base0 + 3072);
        xp[4] = __ldg(g_xproj + base1);
        xp[5] = __ldg(g_xproj + base1 + 1024);
        xp[6] = __ldg(g_xproj + base1 + 2048);
        xp[7] = __ldg(g_xproj + base1 + 3072);
    }

    auto stage_h = [&](int buf, int kc, int hbuf) {
        const __nv_bfloat16* shi = &g_hhi3[hbuf][0];
        const __nv_bfloat16* slo = &g_hlo3[hbuf][0];
        #pragma unroll
        for (int q = 0; q < 4; ++q) {
            const int i = tid + q * 256;
            const int row = i >> 4;
            const int cu = i & 15;
            const size_t src = (size_t)row * Hsz + kc * KC + cu * 8;
            cp16(&hthi[buf][row * (KC + HTPAD) + cu * 8], shi + src);
            cp16(&htlo[buf][row * (KC + HTPAD) + cu * 8], slo + src);
        }
        cp_commit();
    };

    for (int t = 0; t < Lsz; ++t) {
        const int hbuf = t % 3;
        const unsigned need = (unsigned)t * 16;
        float acc[2][4];
        #pragma unroll
        for (int i = 0; i < 2; ++i)
            #pragma unroll
            for (int k = 0; k < 4; ++k) acc[i][k] = 0.0f;

        // wait for region 0's h (step t) then stage chunk 0
        while (ld_acq(&g_rc[0]) < need) { }
        stage_h(0, 0, hbuf);

        for (int kc = 0; kc < NCHUNK; ++kc) {
            const int buf = kc & 1;
            const bool more = (kc + 1) < NCHUNK;
            if (more) {
                while (ld_acq(&g_rc[kc + 1]) < need) { }
                stage_h(buf ^ 1, kc + 1, hbuf);
                cp_wait1();
            } else {
                cp_wait0();
            }
            __syncthreads();

            const __nv_bfloat16* thi = hthi[buf];
            const __nv_bfloat16* tlo = htlo[buf];

            #pragma unroll
            for (int ks = 0; ks < KC / 16; ++ks) {
                const int kb = ks * 16;
                unsigned ahi[4], alo[4], bh[4], bl[4];
                ldsm_x4(ahi, thi + (wm * 16 + aRow) * (KC + HTPAD) + kb + aCol);
                ldsm_x4(alo, tlo + (wm * 16 + aRow) * (KC + HTPAD) + kb + aCol);
                const int koff = kc * KC + kb + bCol;
                ldsm_x4(bh, whhi + bRow * (Hsz + WPAD) + koff);
                ldsm_x4(bl, whlo + bRow * (Hsz + WPAD) + koff);
                mma16816(acc[0], ahi, bh);
                mma16816(acc[0], ahi, bl);
                mma16816(acc[0], alo, bh);
                mma16816(acc[1], ahi, bh + 2);
                mma16816(acc[1], ahi, bl + 2);
                mma16816(acc[1], alo, bh + 2);
            }
            __syncthreads();
        }

        // gate pre-activations -> SMEM
        #pragma unroll
        for (int nt = 0; nt < 2; ++nt) {
            const int c = wn * 16 + nt * 8 + 2 * tg;
            const int r = wm * 16 + g;
            gates[r * NG + c]           = acc[nt][0];
            gates[r * NG + c + 1]       = acc[nt][1];
            gates[(r + 8) * NG + c]     = acc[nt][2];
            gates[(r + 8) * NG + c + 1] = acc[nt][3];
        }
        __syncthreads();

        // LSTM cell (512 items), write h into buffer (t+1)%3
        const int nb = (t + 1) % 3;
        {
            const float pf = gates[b_0 * NG + 0 * 8 + jj_0] + xp[0];
            const float pi = gates[b_0 * NG + 1 * 8 + jj_0] + xp[1];
            const float pg = gates[b_0 * NG + 2 * 8 + jj_0] + xp[2];
            const float po = gates[b_0 * NG + 3 * 8 + jj_0] + xp[3];
            const float f = sigmoidf_(pf);
            const float ii = sigmoidf_(pi);
            const float gg = tanhf(pg);
            const float o = sigmoidf_(po);
            const float c_new = f * csm[tid] + ii * gg;
            csm[tid] = c_new;
            const float h = o * tanhf(c_new);
            out[((size_t)b_0 * Lsz + t) * Hsz + j0 + jj_0] = h;
            const __nv_bfloat16 hh = __float2bfloat16(h);
            g_hhi3[nb][b_0 * Hsz + j0 + jj_0] = hh;
            g_hlo3[nb][b_0 * Hsz + j0 + jj_0] = __float2bfloat16(h - __bfloat162float(hh));
        }
        {
            const float pf = gates[b_1 * NG + 0 * 8 + jj_1] + xp[4];
            const float pi = gates[b_1 * NG + 1 * 8 + jj_1] + xp[5];
            const float pg = gates[b_1 * NG + 2 * 8 + jj_1] + xp[6];
            const float po = gates[b_1 * NG + 3 * 8 + jj_1] + xp[7];
            const float f = sigmoidf_(pf);
            const float ii = sigmoidf_(pi);
            const float gg = tanhf(pg);
            const float o = sigmoidf_(po);
            const float c_new = f * csm[tid + 256] + ii * gg;
            csm[tid + 256] = c_new;
            const float h = o * tanhf(c_new);
            out[((size_t)b_1 * Lsz + t) * Hsz + j0 + jj_1] = h;
            const __nv_bfloat16 hh = __float2bfloat16(h);
            g_hhi3[nb][b_1 * Hsz + j0 + jj_1] = hh;
            g_hlo3[nb][b_1 * Hsz + j0 + jj_1] = __float2bfloat16(h - __bfloat162float(hh));
        }

        // publish: this block finished step t for its region
        __threadfence();
        __syncthreads();
        if (tid == 0) atomicAdd(&g_rc[region], 1u);

        // prefetch xproj for next step (hidden under next step's region waits)
        if (t + 1 < Lsz) {
            const size_t base0 = ((size_t)b_0 * Lsz + (t + 1)) * Gsz + j0 + jj_0;
            const size_t base1 = ((size_t)b_1 * Lsz + (t + 1)) * Gsz + j0 + jj_1;
            xp[0] = __ldg(g_xproj + base0);
            xp[1] = __ldg(g_xproj + base0 + 1024);
            xp[2] = __ldg(g_xproj + base0 + 2048);
            xp[3] = __ldg(g_xproj + base0 + 3072);
            xp[4] = __ldg(g_xproj + base1);
            xp[5] = __ldg(g_xproj + base1 + 1024);
            xp[6] = __ldg(g_xproj + base1 + 2048);
            xp[7] = __ldg(g_xproj + base1 + 3072);
        }
    }

    // finals
    {
        const float hv0 = out[((size_t)b_0 * Lsz + (Lsz - 1)) * Hsz + j0 + jj_0];
        out[OUTN + (size_t)b_0 * Hsz + j0 + jj_0] = hv0;
        out[OUTN + (size_t)Bsz * Hsz + (size_t)b_0 * Hsz + j0 + jj_0] = csm[tid];
        const float hv1 = out[((size_t)b_1 * Lsz + (Lsz - 1)) * Hsz + j0 + jj_1];
        out[OUTN + (size_t)b_1 * Hsz + j0 + jj_1] = hv1;
        out[OUTN + (size_t)Bsz * Hsz + (size_t)b_1 * Hsz + j0 + jj_1] = csm[tid + 256];
    }
}

// ---------------- launcher ----------------
extern "C" void kernel_launch(void* const* d_in, const int* in_sizes, int n_in,
                              void* d_out, int out_size) {
    const float* x = (const float*)d_in[0];
    const float* W = (const float*)d_in[1];
    const float* b = (const float*)d_in[2];
    float* out = (float*)d_out;

    split_x_kernel<<<2048, 256>>>(x);
    split_w_kernel<<<1024, 256>>>(W);
    init_kernel<<<256, 256>>>();

    dim3 g1(Gsz / P1_BN, ML / P1_BM);   // (32, 256)
    xproj_kernel<<<g1, 256>>>(b);

    cudaFuncSetAttribute(lstm_kernel, cudaFuncAttributeMaxDynamicSharedMemorySize,
                         (int)SMEM_P2);
    lstm_kernel<<<NBLK2, 256, SMEM_P2>>>(out);
}